// round 6
// baseline (speedup 1.0000x reference)
#include <cuda_runtime.h>
#include <cuda_bf16.h>
#include <math.h>
#include <stdint.h>

#define BB 2
#define SS 2048
#define DM 1024
#define NH 16
#define DKK 64
#define DFF 4096
#define MT (BB*SS)   // 4096 tokens

// ---------------- scratch (__device__ globals; no allocations) ----------------
__device__ float g_xn [(size_t)MT*DM];
__device__ float g_lin[(size_t)3*MT*DM];
__device__ float g_q  [(size_t)MT*DM];
__device__ float g_k  [(size_t)MT*DM];
__device__ float g_v  [(size_t)MT*DM];
__device__ float g_att[(size_t)MT*DM];
__device__ float g_x1 [(size_t)MT*DM];
__device__ float g_a  [(size_t)MT*DFF];
__device__ float g_g  [(size_t)MT*DFF];

// ================= helpers =================
__device__ __forceinline__ uint32_t smem_u32(const void* p) {
    uint32_t a;
    asm("{ .reg .u64 t; cvta.to.shared.u64 t, %1; cvt.u32.u64 %0, t; }" : "=r"(a) : "l"(p));
    return a;
}
__device__ __forceinline__ void ldm_x4(uint32_t* r, uint32_t addr) {
    asm volatile("ldmatrix.sync.aligned.m8n8.x4.shared.b16 {%0,%1,%2,%3}, [%4];"
        : "=r"(r[0]),"=r"(r[1]),"=r"(r[2]),"=r"(r[3]) : "r"(addr));
}
__device__ __forceinline__ void ldm_x4t(uint32_t* r, uint32_t addr) {
    asm volatile("ldmatrix.sync.aligned.m8n8.x4.trans.shared.b16 {%0,%1,%2,%3}, [%4];"
        : "=r"(r[0]),"=r"(r[1]),"=r"(r[2]),"=r"(r[3]) : "r"(addr));
}
__device__ __forceinline__ void mma_bf16(float* d,
        uint32_t a0, uint32_t a1, uint32_t a2, uint32_t a3,
        uint32_t b0, uint32_t b1) {
    asm volatile("mma.sync.aligned.m16n8k16.row.col.f32.bf16.bf16.f32 "
        "{%0,%1,%2,%3}, {%4,%5,%6,%7}, {%8,%9}, {%0,%1,%2,%3};"
        : "+f"(d[0]),"+f"(d[1]),"+f"(d[2]),"+f"(d[3])
        : "r"(a0),"r"(a1),"r"(a2),"r"(a3),"r"(b0),"r"(b1));
}
__device__ __forceinline__ void cp16(uint32_t dst, const void* src) {
    asm volatile("cp.async.cg.shared.global [%0], [%1], 16;" :: "r"(dst), "l"(src));
}
#define CP_COMMIT() asm volatile("cp.async.commit_group;" ::: "memory")
#define CP_WAIT1()  asm volatile("cp.async.wait_group 1;" ::: "memory")
#define CP_WAIT0()  asm volatile("cp.async.wait_group 0;" ::: "memory")

__device__ __forceinline__ uint32_t pack_bf2(float a, float b) {
    __nv_bfloat162 t = __floats2bfloat162_rn(a, b);
    return *reinterpret_cast<uint32_t*>(&t);
}
// split fp32x4 -> 4 bf16 hi (8B) + 4 bf16 lo (8B), store to smem
__device__ __forceinline__ void cvt_split8(uint32_t hi_addr, uint32_t lo_addr, float4 v) {
    uint32_t u0 = pack_bf2(v.x, v.y);
    uint32_t u1 = pack_bf2(v.z, v.w);
    float rx = v.x - __uint_as_float(u0 << 16);
    float ry = v.y - __uint_as_float(u0 & 0xffff0000u);
    float rz = v.z - __uint_as_float(u1 << 16);
    float rw = v.w - __uint_as_float(u1 & 0xffff0000u);
    uint32_t w0 = pack_bf2(rx, ry);
    uint32_t w1 = pack_bf2(rz, rw);
    asm volatile("st.shared.v2.b32 [%0], {%1, %2};" :: "r"(hi_addr), "r"(u0), "r"(u1));
    asm volatile("st.shared.v2.b32 [%0], {%1, %2};" :: "r"(lo_addr), "r"(w0), "r"(w1));
}

// ================= split-bf16 tensor-core GEMM (mma.sync, 512 threads) =================
#define BK 32
#define ROWB 80
#define MATB (128*ROWB)
#define STAGEB (4*MATB)
#define GEMM_SMEM (2*STAGEB)

__global__ void __launch_bounds__(512, 1) gemm_mma(
    const float* __restrict__ A, const float* __restrict__ B,
    const float* __restrict__ R, float* __restrict__ C,
    int M, int N, int K)
{
    extern __shared__ char smem[];
    const uint32_t sb = smem_u32(smem);
    const int tid = threadIdx.x;
    const int wid = tid >> 5, lane = tid & 31;
    const int bm = blockIdx.y * 128, bn = blockIdx.x * 128;
    const int wm = (wid & 3) * 32, wn = (wid >> 2) * 32;

    const int a_r16 = lane & 15, a_kh = lane >> 4;
    const int b_row = (lane & 7) + ((lane & 16) ? 8 : 0);
    const int b_kh = (lane >> 3) & 1;

    float acc[2][4][4];
    #pragma unroll
    for (int mi = 0; mi < 2; mi++)
        #pragma unroll
        for (int ni = 0; ni < 4; ni++)
            #pragma unroll
            for (int r = 0; r < 4; r++) acc[mi][ni][r] = 0.f;

    const int NC = K >> 5;
    {
        const float* At = A + (size_t)bm * K;
        const float* Bt = B + (size_t)bn * K;
        #pragma unroll
        for (int i = 0; i < 2; i++) {
            int idx = tid + i * 512;
            int row = idx >> 3, f4 = idx & 7;
            uint32_t off = (uint32_t)(row * ROWB + f4 * 8);
            float4 av = *(const float4*)(At + (size_t)row * K + f4 * 4);
            cvt_split8(sb + off, sb + MATB + off, av);
            float4 bv = *(const float4*)(Bt + (size_t)row * K + f4 * 4);
            cvt_split8(sb + 2*MATB + off, sb + 3*MATB + off, bv);
        }
    }
    __syncthreads();

    for (int c = 0; c < NC; c++) {
        const int stg = c & 1;
        const uint32_t base = sb + stg * STAGEB;

        float4 aw[2], bw[2];
        if (c + 1 < NC) {
            const float* At = A + (size_t)bm * K + (c + 1) * BK;
            const float* Bt = B + (size_t)bn * K + (c + 1) * BK;
            #pragma unroll
            for (int i = 0; i < 2; i++) {
                int idx = tid + i * 512;
                int row = idx >> 3, f4 = idx & 7;
                aw[i] = *(const float4*)(At + (size_t)row * K + f4 * 4);
                bw[i] = *(const float4*)(Bt + (size_t)row * K + f4 * 4);
            }
        }

        #pragma unroll
        for (int kk = 0; kk < 2; kk++) {
            uint32_t ah[2][4], al[2][4], bh[2][4], bl[2][4];
            #pragma unroll
            for (int mi = 0; mi < 2; mi++) {
                uint32_t ad = base + (uint32_t)((wm + mi*16 + a_r16) * ROWB + kk*32 + a_kh*16);
                ldm_x4(ah[mi], ad);
                ldm_x4(al[mi], ad + MATB);
            }
            #pragma unroll
            for (int p = 0; p < 2; p++) {
                uint32_t bd = base + (uint32_t)(2*MATB
                            + (wn + p*16 + b_row) * ROWB + kk*32 + b_kh*16);
                ldm_x4(bh[p], bd);
                ldm_x4(bl[p], bd + MATB);
            }
            #pragma unroll
            for (int mi = 0; mi < 2; mi++) {
                #pragma unroll
                for (int ni = 0; ni < 4; ni++) {
                    const int p = ni >> 1, s = (ni & 1) * 2;
                    mma_bf16(acc[mi][ni], ah[mi][0], ah[mi][1], ah[mi][2], ah[mi][3],
                             bh[p][s], bh[p][s+1]);
                    mma_bf16(acc[mi][ni], ah[mi][0], ah[mi][1], ah[mi][2], ah[mi][3],
                             bl[p][s], bl[p][s+1]);
                    mma_bf16(acc[mi][ni], al[mi][0], al[mi][1], al[mi][2], al[mi][3],
                             bh[p][s], bh[p][s+1]);
                }
            }
        }

        if (c + 1 < NC) {
            const uint32_t nb = sb + (stg ^ 1) * STAGEB;
            #pragma unroll
            for (int i = 0; i < 2; i++) {
                int idx = tid + i * 512;
                int row = idx >> 3, f4 = idx & 7;
                uint32_t off = (uint32_t)(row * ROWB + f4 * 8);
                cvt_split8(nb + off, nb + MATB + off, aw[i]);
                cvt_split8(nb + 2*MATB + off, nb + 3*MATB + off, bw[i]);
            }
        }
        __syncthreads();
    }

    const int g = lane >> 2, tg = lane & 3;
    #pragma unroll
    for (int mi = 0; mi < 2; mi++) {
        #pragma unroll
        for (int ni = 0; ni < 4; ni++) {
            int r0 = bm + wm + mi*16 + g;
            int c0 = bn + wn + ni*8 + tg*2;
            float* d = acc[mi][ni];
            if (R) {
                float2 rv0 = *(const float2*)(R + (size_t)r0 * N + c0);
                float2 rv1 = *(const float2*)(R + (size_t)(r0+8) * N + c0);
                *(float2*)(C + (size_t)r0 * N + c0)     = make_float2(d[0]+rv0.x, d[1]+rv0.y);
                *(float2*)(C + (size_t)(r0+8) * N + c0) = make_float2(d[2]+rv1.x, d[3]+rv1.y);
            } else {
                *(float2*)(C + (size_t)r0 * N + c0)     = make_float2(d[0], d[1]);
                *(float2*)(C + (size_t)(r0+8) * N + c0) = make_float2(d[2], d[3]);
            }
        }
    }
}

// ---------------- rmsnorm ----------------
__global__ void rmsnorm_k(const float* __restrict__ x, const float* __restrict__ w,
                          float* __restrict__ out) {
    int row = blockIdx.x;
    int t = threadIdx.x;
    float4 xv = ((const float4*)(x + (size_t)row*DM))[t];
    float s = xv.x*xv.x + xv.y*xv.y + xv.z*xv.z + xv.w*xv.w;
    #pragma unroll
    for (int o = 16; o > 0; o >>= 1) s += __shfl_xor_sync(0xffffffffu, s, o);
    __shared__ float ws[8];
    __shared__ float s_inv;
    if ((t & 31) == 0) ws[t >> 5] = s;
    __syncthreads();
    if (t == 0) {
        float tot = 0.f;
        #pragma unroll
        for (int i = 0; i < 8; i++) tot += ws[i];
        s_inv = rsqrtf(tot / (float)DM + 1e-5f);
    }
    __syncthreads();
    float inv = s_inv;
    float4 wv = ((const float4*)w)[t];
    float4 ov;
    ov.x = xv.x*inv*wv.x; ov.y = xv.y*inv*wv.y;
    ov.z = xv.z*inv*wv.z; ov.w = xv.w*inv*wv.w;
    ((float4*)(out + (size_t)row*DM))[t] = ov;
}

// ---------------- RoPE + head permute ----------------
__global__ void rope_perm_k(const float* __restrict__ lin, const int* __restrict__ pos,
                            float* __restrict__ q, float* __restrict__ k,
                            float* __restrict__ v) {
    int idx = blockIdx.x * blockDim.x + threadIdx.x;
    if (idx >= MT * NH * (DKK/2)) return;
    int i  = idx & 31;
    int hh = (idx >> 5) & (NH-1);
    int t  = idx >> 9;
    int b  = t >> 11;
    int s  = t & (SS - 1);
    size_t src = (size_t)t * DM + hh * DKK + 2*i;
    size_t dst = ((size_t)(b*NH + hh) * SS + s) * DKK + 2*i;
    double ex = -((double)(2*i) / 64.0) * 9.210340371976184;
    float invf = (float)exp(ex);
    float ang = (float)pos[t] * invf;
    float sn, cs;
    sincosf(ang, &sn, &cs);
    float qe = lin[src], qo = lin[src+1];
    q[dst]   = qe*cs - qo*sn;
    q[dst+1] = qe*sn + qo*cs;
    const float* link = lin + (size_t)MT*DM;
    float ke = link[src], ko = link[src+1];
    k[dst]   = ke*cs - ko*sn;
    k[dst+1] = ke*sn + ko*cs;
    const float* linv = lin + (size_t)2*MT*DM;
    v[dst]   = linv[src];
    v[dst+1] = linv[src+1];
}

// ================= tensor-core flash attention (split-bf16, causal) =================
// BM=128 Q-rows/CTA, BN=64 keys/tile, 8 warps (each warp: 16 rows x full tile).
#define AT_STRB 144                 // bytes per row in bf16 tiles (64*2 + 16 pad)
#define AT_QB  (128*AT_STRB)        // 18432 per Q matrix (hi or lo)
#define AT_KB  (64*AT_STRB)         // 9216 per K/V matrix (hi or lo)
#define AT_RAW (64*64*4)            // 16384 raw fp32 per matrix
// layout: Qh | Ql | Kh | Kl | Vh | Vl | raw0(K,V) | raw1(K,V)
#define O_QH 0
#define O_QL AT_QB
#define O_KH (2*AT_QB)
#define O_KL (O_KH + AT_KB)
#define O_VH (O_KH + 2*AT_KB)
#define O_VL (O_KH + 3*AT_KB)
#define O_RAW (O_KH + 4*AT_KB)
#define ATT_SMEM (O_RAW + 4*AT_RAW)   // 73728 + 65536 = 139264

__global__ void __launch_bounds__(256, 1) attn_mma(
    const float* __restrict__ Q, const float* __restrict__ Kg,
    const float* __restrict__ Vg, float* __restrict__ O)
{
    extern __shared__ char smem[];
    const uint32_t sb = smem_u32(smem);
    const int qt = blockIdx.x, h = blockIdx.y, b = blockIdx.z;
    const int tid = threadIdx.x;
    const int wid = tid >> 5, lane = tid & 31;
    const int q0 = qt * 128;
    const float* Qp = Q  + ((size_t)(b*NH + h) * SS + q0) * DKK;
    const float* Kp = Kg + (size_t)(b*NH + h) * SS * DKK;
    const float* Vp = Vg + (size_t)(b*NH + h) * SS * DKK;

    const int nkt = (q0 >> 6) + 2;

    // prologue: cp.async raw tile 0 (K then V), 4 x 16B each per thread
    {
        const uint32_t r0b = sb + O_RAW;
        #pragma unroll
        for (int i = 0; i < 4; i++) {
            int idx = tid + i * 256;
            int row = idx >> 4, f4 = idx & 15;
            cp16(r0b + (uint32_t)(row*256 + f4*16), Kp + (size_t)row*DKK + f4*4);
            cp16(r0b + (uint32_t)(AT_RAW + row*256 + f4*16), Vp + (size_t)row*DKK + f4*4);
        }
        CP_COMMIT();
    }

    // load Q tile, scale by 1/8, split to hi/lo smem
    #pragma unroll
    for (int i = 0; i < 8; i++) {
        int idx = tid + i * 256;
        int row = idx >> 4, f4 = idx & 15;
        float4 v = *(const float4*)(Qp + (size_t)row*DKK + f4*4);
        v.x *= 0.125f; v.y *= 0.125f; v.z *= 0.125f; v.w *= 0.125f;
        uint32_t off = (uint32_t)(row*AT_STRB + f4*8);
        cvt_split8(sb + O_QH + off, sb + O_QL + off, v);
    }
    __syncthreads();

    // per-warp Q fragments
    const int a_r16 = lane & 15, a_kh = lane >> 4;
    uint32_t qh[4][4], ql[4][4];
    #pragma unroll
    for (int kk = 0; kk < 4; kk++) {
        uint32_t ad = sb + O_QH + (uint32_t)((wid*16 + a_r16)*AT_STRB + kk*32 + a_kh*16);
        ldm_x4(qh[kk], ad);
        ldm_x4(ql[kk], ad + AT_QB);
    }

    float o[8][4];
    #pragma unroll
    for (int nd = 0; nd < 8; nd++)
        #pragma unroll
        for (int r = 0; r < 4; r++) o[nd][r] = 0.f;
    float mrow0 = -1e30f, mrow1 = -1e30f, lrow0 = 0.f, lrow1 = 0.f;

    const int b_row = (lane & 7) + ((lane & 16) ? 8 : 0);
    const int b_kh = (lane >> 3) & 1;
    const bool warp_any = true;
    const int wrow_max = q0 + wid*16 + 15;

    for (int kt = 0; kt < nkt; kt++) {
        // prefetch raw tile kt+1
        if (kt + 1 < nkt) {
            const uint32_t rb = sb + O_RAW + (uint32_t)(((kt+1) & 1) * 2 * AT_RAW);
            const int k0n = (kt + 1) * 64;
            #pragma unroll
            for (int i = 0; i < 4; i++) {
                int idx = tid + i * 256;
                int row = idx >> 4, f4 = idx & 15;
                cp16(rb + (uint32_t)(row*256 + f4*16), Kp + (size_t)(k0n+row)*DKK + f4*4);
                cp16(rb + (uint32_t)(AT_RAW + row*256 + f4*16), Vp + (size_t)(k0n+row)*DKK + f4*4);
            }
            CP_COMMIT();
            CP_WAIT1();
        } else {
            CP_WAIT0();
        }

        // convert raw[kt&1] -> bf16 K/V buffers (each thread converts its own cp'd bytes)
        {
            const uint32_t rb = sb + O_RAW + (uint32_t)((kt & 1) * 2 * AT_RAW);
            #pragma unroll
            for (int i = 0; i < 4; i++) {
                int idx = tid + i * 256;
                int row = idx >> 4, f4 = idx & 15;
                uint32_t off = (uint32_t)(row*AT_STRB + f4*8);
                float4 kv, vv;
                asm volatile("ld.shared.v4.b32 {%0,%1,%2,%3}, [%4];"
                    : "=f"(kv.x),"=f"(kv.y),"=f"(kv.z),"=f"(kv.w)
                    : "r"(rb + (uint32_t)(row*256 + f4*16)));
                asm volatile("ld.shared.v4.b32 {%0,%1,%2,%3}, [%4];"
                    : "=f"(vv.x),"=f"(vv.y),"=f"(vv.z),"=f"(vv.w)
                    : "r"(rb + (uint32_t)(AT_RAW + row*256 + f4*16)));
                cvt_split8(sb + O_KH + off, sb + O_KL + off, kv);
                cvt_split8(sb + O_VH + off, sb + O_VL + off, vv);
            }
        }
        __syncthreads();

        if (kt*64 <= wrow_max) {
            // ---- S = Q K^T ----
            float s[8][4];
            #pragma unroll
            for (int ni = 0; ni < 8; ni++)
                #pragma unroll
                for (int r = 0; r < 4; r++) s[ni][r] = 0.f;
            #pragma unroll
            for (int kk = 0; kk < 4; kk++) {
                uint32_t bh[4][4], bl[4][4];
                #pragma unroll
                for (int p = 0; p < 4; p++) {
                    uint32_t bd = sb + O_KH + (uint32_t)((p*16 + b_row)*AT_STRB + kk*32 + b_kh*16);
                    ldm_x4(bh[p], bd);
                    ldm_x4(bl[p], bd + AT_KB);
                }
                #pragma unroll
                for (int ni = 0; ni < 8; ni++) {
                    const int p = ni >> 1, sx = (ni & 1) * 2;
                    mma_bf16(s[ni], qh[kk][0], qh[kk][1], qh[kk][2], qh[kk][3],
                             bh[p][sx], bh[p][sx+1]);
                    mma_bf16(s[ni], qh[kk][0], qh[kk][1], qh[kk][2], qh[kk][3],
                             bl[p][sx], bl[p][sx+1]);
                    mma_bf16(s[ni], ql[kk][0], ql[kk][1], ql[kk][2], ql[kk][3],
                             bh[p][sx], bh[p][sx+1]);
                }
            }
            // ---- mask ----
            const int r0 = q0 + wid*16 + (lane >> 2);
            const int r1 = r0 + 8;
            const int cb = kt*64 + (lane & 3)*2;
            #pragma unroll
            for (int ni = 0; ni < 8; ni++) {
                int c = cb + ni*8;
                if (c     > r0) s[ni][0] = -1e30f;
                if (c + 1 > r0) s[ni][1] = -1e30f;
                if (c     > r1) s[ni][2] = -1e30f;
                if (c + 1 > r1) s[ni][3] = -1e30f;
            }
            // ---- online softmax ----
            float mx0 = -1e30f, mx1 = -1e30f;
            #pragma unroll
            for (int ni = 0; ni < 8; ni++) {
                mx0 = fmaxf(mx0, fmaxf(s[ni][0], s[ni][1]));
                mx1 = fmaxf(mx1, fmaxf(s[ni][2], s[ni][3]));
            }
            mx0 = fmaxf(mx0, __shfl_xor_sync(0xffffffffu, mx0, 1));
            mx0 = fmaxf(mx0, __shfl_xor_sync(0xffffffffu, mx0, 2));
            mx1 = fmaxf(mx1, __shfl_xor_sync(0xffffffffu, mx1, 1));
            mx1 = fmaxf(mx1, __shfl_xor_sync(0xffffffffu, mx1, 2));
            float mn0 = fmaxf(mrow0, mx0), mn1 = fmaxf(mrow1, mx1);
            float al0 = __expf(mrow0 - mn0), al1 = __expf(mrow1 - mn1);
            float sum0 = 0.f, sum1 = 0.f;
            #pragma unroll
            for (int ni = 0; ni < 8; ni++) {
                s[ni][0] = __expf(s[ni][0] - mn0);
                s[ni][1] = __expf(s[ni][1] - mn0);
                s[ni][2] = __expf(s[ni][2] - mn1);
                s[ni][3] = __expf(s[ni][3] - mn1);
                sum0 += s[ni][0] + s[ni][1];
                sum1 += s[ni][2] + s[ni][3];
            }
            sum0 += __shfl_xor_sync(0xffffffffu, sum0, 1);
            sum0 += __shfl_xor_sync(0xffffffffu, sum0, 2);
            sum1 += __shfl_xor_sync(0xffffffffu, sum1, 1);
            sum1 += __shfl_xor_sync(0xffffffffu, sum1, 2);
            lrow0 = lrow0 * al0 + sum0;
            lrow1 = lrow1 * al1 + sum1;
            mrow0 = mn0; mrow1 = mn1;
            #pragma unroll
            for (int nd = 0; nd < 8; nd++) {
                o[nd][0] *= al0; o[nd][1] *= al0;
                o[nd][2] *= al1; o[nd][3] *= al1;
            }
            // ---- P fragments (hi/lo) in A layout ----
            uint32_t ph[4][4], pl[4][4];
            #pragma unroll
            for (int kb = 0; kb < 4; kb++) {
                float v0, v1;
                // a0: (r0, k0k1) ; a1: (r0+8, k0k1) ; a2: (r0, k8k9) ; a3: (r0+8, k8k9)
                v0 = s[2*kb][0];   v1 = s[2*kb][1];
                ph[kb][0] = pack_bf2(v0, v1);
                pl[kb][0] = pack_bf2(v0 - __uint_as_float(ph[kb][0] << 16),
                                     v1 - __uint_as_float(ph[kb][0] & 0xffff0000u));
                v0 = s[2*kb][2];   v1 = s[2*kb][3];
                ph[kb][1] = pack_bf2(v0, v1);
                pl[kb][1] = pack_bf2(v0 - __uint_as_float(ph[kb][1] << 16),
                                     v1 - __uint_as_float(ph[kb][1] & 0xffff0000u));
                v0 = s[2*kb+1][0]; v1 = s[2*kb+1][1];
                ph[kb][2] = pack_bf2(v0, v1);
                pl[kb][2] = pack_bf2(v0 - __uint_as_float(ph[kb][2] << 16),
                                     v1 - __uint_as_float(ph[kb][2] & 0xffff0000u));
                v0 = s[2*kb+1][2]; v1 = s[2*kb+1][3];
                ph[kb][3] = pack_bf2(v0, v1);
                pl[kb][3] = pack_bf2(v0 - __uint_as_float(ph[kb][3] << 16),
                                     v1 - __uint_as_float(ph[kb][3] & 0xffff0000u));
            }
            // ---- O += P V ----
            #pragma unroll
            for (int p = 0; p < 4; p++) {
                #pragma unroll
                for (int kb = 0; kb < 4; kb++) {
                    uint32_t vd = sb + O_VH + (uint32_t)((kb*16 + (lane & 15))*AT_STRB
                                + (p*16 + (lane >> 4)*8)*2);
                    uint32_t vh4[4], vl4[4];
                    ldm_x4t(vh4, vd);
                    ldm_x4t(vl4, vd + AT_KB);
                    const int nd0 = 2*p, nd1 = 2*p + 1;
                    mma_bf16(o[nd0], ph[kb][0], ph[kb][1], ph[kb][2], ph[kb][3], vh4[0], vh4[1]);
                    mma_bf16(o[nd0], pl[kb][0], pl[kb][1], pl[kb][2], pl[kb][3], vh4[0], vh4[1]);
                    mma_bf16(o[nd0], ph[kb][0], ph[kb][1], ph[kb][2], ph[kb][3], vl4[0], vl4[1]);
                    mma_bf16(o[nd1], ph[kb][0], ph[kb][1], ph[kb][2], ph[kb][3], vh4[2], vh4[3]);
                    mma_bf16(o[nd1], pl[kb][0], pl[kb][1], pl[kb][2], pl[kb][3], vh4[2], vh4[3]);
                    mma_bf16(o[nd1], ph[kb][0], ph[kb][1], ph[kb][2], ph[kb][3], vl4[2], vl4[3]);
                }
            }
        }
        __syncthreads();
    }

    // epilogue
    const float inv0 = 1.f / lrow0, inv1 = 1.f / lrow1;
    const int r0g = q0 + wid*16 + (lane >> 2);
    const int r1g = r0g + 8;
    #pragma unroll
    for (int nd = 0; nd < 8; nd++) {
        int c = h*DKK + nd*8 + (lane & 3)*2;
        *(float2*)(O + (size_t)(b*SS + r0g)*DM + c) = make_float2(o[nd][0]*inv0, o[nd][1]*inv0);
        *(float2*)(O + (size_t)(b*SS + r1g)*DM + c) = make_float2(o[nd][2]*inv1, o[nd][3]*inv1);
    }
}

// ---------------- silu(a) * g ----------------
__global__ void silu_mul_k(float4* __restrict__ a, const float4* __restrict__ g, int n4) {
    int i = blockIdx.x * blockDim.x + threadIdx.x;
    if (i >= n4) return;
    float4 av = a[i], gv = g[i], r;
    r.x = (av.x / (1.f + __expf(-av.x))) * gv.x;
    r.y = (av.y / (1.f + __expf(-av.y))) * gv.y;
    r.z = (av.z / (1.f + __expf(-av.z))) * gv.z;
    r.w = (av.w / (1.f + __expf(-av.w))) * gv.w;
    a[i] = r;
}

// ---------------- launcher ----------------
extern "C" void kernel_launch(void* const* d_in, const int* in_sizes, int n_in,
                              void* d_out, int out_size) {
    const float* x   = (const float*)d_in[0];
    const int*   pos = (const int*)  d_in[1];
    const float* n1w = (const float*)d_in[2];
    const float* n2w = (const float*)d_in[3];
    const float* wq  = (const float*)d_in[4];
    const float* wk  = (const float*)d_in[5];
    const float* wv  = (const float*)d_in[6];
    const float* wo  = (const float*)d_in[7];
    const float* w1  = (const float*)d_in[8];
    const float* w2  = (const float*)d_in[9];
    const float* w3  = (const float*)d_in[10];
    float* out = (float*)d_out;

    float *xn, *lin, *q, *k, *v, *att, *x1, *a, *g;
    cudaGetSymbolAddress((void**)&xn,  g_xn);
    cudaGetSymbolAddress((void**)&lin, g_lin);
    cudaGetSymbolAddress((void**)&q,   g_q);
    cudaGetSymbolAddress((void**)&k,   g_k);
    cudaGetSymbolAddress((void**)&v,   g_v);
    cudaGetSymbolAddress((void**)&att, g_att);
    cudaGetSymbolAddress((void**)&x1,  g_x1);
    cudaGetSymbolAddress((void**)&a,   g_a);
    cudaGetSymbolAddress((void**)&g,   g_g);

    cudaFuncSetAttribute(attn_mma, cudaFuncAttributeMaxDynamicSharedMemorySize, ATT_SMEM);
    cudaFuncSetAttribute(gemm_mma, cudaFuncAttributeMaxDynamicSharedMemorySize, GEMM_SMEM);

    rmsnorm_k<<<MT, 256>>>(x, n1w, xn);
    gemm_mma<<<dim3(DM/128, MT/128), 512, GEMM_SMEM>>>(xn, wq, nullptr, lin,                   MT, DM, DM);
    gemm_mma<<<dim3(DM/128, MT/128), 512, GEMM_SMEM>>>(xn, wk, nullptr, lin + (size_t)MT*DM,   MT, DM, DM);
    gemm_mma<<<dim3(DM/128, MT/128), 512, GEMM_SMEM>>>(xn, wv, nullptr, lin + (size_t)2*MT*DM, MT, DM, DM);
    rope_perm_k<<<(MT*NH*(DKK/2))/256, 256>>>(lin, pos, q, k, v);
    attn_mma<<<dim3(SS/128, NH, BB), 256, ATT_SMEM>>>(q, k, v, att);
    gemm_mma<<<dim3(DM/128, MT/128), 512, GEMM_SMEM>>>(att, wo, x, x1, MT, DM, DM);
    rmsnorm_k<<<MT, 256>>>(x1, n2w, xn);
    gemm_mma<<<dim3(DFF/128, MT/128), 512, GEMM_SMEM>>>(xn, w1, nullptr, a, MT, DFF, DM);
    gemm_mma<<<dim3(DFF/128, MT/128), 512, GEMM_SMEM>>>(xn, w3, nullptr, g, MT, DFF, DM);
    silu_mul_k<<<(MT*DFF/4 + 255)/256, 256>>>((float4*)a, (const float4*)g, MT*DFF/4);
    gemm_mma<<<dim3(DM/128, MT/128), 512, GEMM_SMEM>>>(a, w2, x1, out, MT, DM, DFF);
}